// round 15
// baseline (speedup 1.0000x reference)
#include <cuda_runtime.h>
#include <cuda_fp16.h>
#include <cstdint>
#include <cmath>

// ---------------- problem constants ----------------
#define T_TOK   4096
#define D_MODEL 1024
#define E_NUM   8
#define K_TOP   2
#define CAPACITY 1280
#define H_DIM   4096
#define NYMAX   (CAPACITY / 128)

// ---------------- device scratch ----------------
__device__ __half g_xe   [(size_t)E_NUM * CAPACITY * D_MODEL];
__device__ __half g_h    [(size_t)E_NUM * CAPACITY * H_DIM];
__device__ __half g_wfch [(size_t)E_NUM * D_MODEL * H_DIM];
__device__ __half g_wprojh[(size_t)E_NUM * H_DIM * D_MODEL];
__device__ int   g_topi[K_TOP * T_TOK];
__device__ float g_p   [K_TOP * T_TOK];
__device__ int   g_rank[K_TOP * T_TOK];
__device__ int   g_slot[E_NUM * CAPACITY];
__device__ int   g_kcnt[E_NUM];
__device__ int   g_blkcnt[E_NUM];
__device__ float g_prob_sums[E_NUM];
__device__ float g_zsum;

// ---------------- helpers ----------------
__device__ __forceinline__ float gelu_exact(float v) {
    return 0.5f * v * (1.f + erff(v * 0.70710678118654752440f));
}
__device__ __forceinline__ uint32_t h2f_bits(uint32_t w, int sh) {
    __half h = __ushort_as_half((unsigned short)(w >> sh));
    return __float_as_uint(__half2float(h));
}

#define CP16(dst, src) \
    asm volatile("cp.async.cg.shared.global [%0], [%1], 16;" \
                 :: "r"(dst), "l"(src) : "memory")
#define CPCOMMIT() asm volatile("cp.async.commit_group;" ::: "memory")
#define CPWAIT1()  asm volatile("cp.async.wait_group 1;" ::: "memory")

#define MMA_TF32(c, a, b) \
    asm volatile("mma.sync.aligned.m16n8k8.row.col.f32.tf32.tf32.f32 " \
                 "{%0,%1,%2,%3}, {%4,%5,%6,%7}, {%8,%9}, {%0,%1,%2,%3};" \
                 : "+f"((c)[0]), "+f"((c)[1]), "+f"((c)[2]), "+f"((c)[3]) \
                 : "r"((a)[0]), "r"((a)[1]), "r"((a)[2]), "r"((a)[3]), \
                   "r"((b)[0]), "r"((b)[1]))

// ---------------- weight convert: fp32 -> fp16 elementwise ---------------
__global__ void wconv_kernel(const float* __restrict__ src, __half* __restrict__ dst,
                             size_t n4) {
    const float4* s4 = (const float4*)src;
    uint2* d4 = (uint2*)dst;
    for (size_t i = (size_t)blockIdx.x * blockDim.x + threadIdx.x; i < n4;
         i += (size_t)gridDim.x * blockDim.x) {
        float4 v = s4[i];
        __half2 h0 = __floats2half2_rn(v.x, v.y);
        __half2 h1 = __floats2half2_rn(v.z, v.w);
        uint2 o;
        o.x = *(uint32_t*)&h0;
        o.y = *(uint32_t*)&h1;
        d4[i] = o;
    }
}

// ---------------- zero output ----------------
__global__ void zero_out_kernel(float* __restrict__ out) {
    const size_t n = (size_t)T_TOK * D_MODEL / 4;
    float4 z = make_float4(0.f, 0.f, 0.f, 0.f);
    float4* p = (float4*)out;
    for (size_t i = (size_t)blockIdx.x * blockDim.x + threadIdx.x; i < n;
         i += (size_t)gridDim.x * blockDim.x)
        p[i] = z;
}

// ---------------- init: loss accumulators ----------------
__global__ void init_kernel() {
    const int i = threadIdx.x;
    if (i < E_NUM) g_prob_sums[i] = 0.f;
    if (i == 0)    g_zsum = 0.f;
}

// ---------------- router: warp-per-token ----------------
__global__ void __launch_bounds__(256) router_kernel(const float* __restrict__ x,
                                                     const float* __restrict__ wg) {
    const int wid  = threadIdx.x >> 5;
    const int lane = threadIdx.x & 31;
    const int t    = blockIdx.x * 8 + wid;

    float acc[E_NUM];
#pragma unroll
    for (int e = 0; e < E_NUM; e++) acc[e] = 0.f;

    const float4* x4 = (const float4*)(x + (size_t)t * D_MODEL);
#pragma unroll
    for (int p = 0; p < 8; p++) {
        const int d4 = p * 32 + lane;
        float4 v = x4[d4];
        const float* w = wg + (size_t)d4 * 4 * E_NUM;
#pragma unroll
        for (int e = 0; e < E_NUM; e++) acc[e] += v.x * w[e];
#pragma unroll
        for (int e = 0; e < E_NUM; e++) acc[e] += v.y * w[E_NUM + e];
#pragma unroll
        for (int e = 0; e < E_NUM; e++) acc[e] += v.z * w[2 * E_NUM + e];
#pragma unroll
        for (int e = 0; e < E_NUM; e++) acc[e] += v.w * w[3 * E_NUM + e];
    }
#pragma unroll
    for (int off = 16; off > 0; off >>= 1)
#pragma unroll
        for (int e = 0; e < E_NUM; e++)
            acc[e] += __shfl_xor_sync(0xFFFFFFFFu, acc[e], off);

    __shared__ float blk_p[8][E_NUM];
    __shared__ float blk_z[8];
    if (lane == 0) {
        float l[E_NUM];
#pragma unroll
        for (int e = 0; e < E_NUM; e++) l[e] = acc[e];
        float m = l[0];
#pragma unroll
        for (int e = 1; e < E_NUM; e++) m = fmaxf(m, l[e]);
        float se = 0.f;
#pragma unroll
        for (int e = 0; e < E_NUM; e++) se += expf(l[e] - m);
        float inv = 1.f / se;
#pragma unroll
        for (int e = 0; e < E_NUM; e++) blk_p[wid][e] = expf(l[e] - m) * inv;
        float lse = m + logf(se);
        blk_z[wid] = lse * lse;

        float v1 = -3.4e38f, v2 = -3.4e38f;
        int i1 = 0, i2 = 0;
#pragma unroll
        for (int e = 0; e < E_NUM; e++) {
            float v = l[e];
            if (v > v1) { v2 = v1; i2 = i1; v1 = v; i1 = e; }
            else if (v > v2) { v2 = v; i2 = e; }
        }
        float e2 = expf(v2 - v1);
        float s2 = 1.f + e2;
        g_topi[t]         = i1;
        g_topi[T_TOK + t] = i2;
        g_p[t]            = 1.f / s2;
        g_p[T_TOK + t]    = e2 / s2;
    }
    __syncthreads();
    if (threadIdx.x < E_NUM) {
        float s = 0.f;
#pragma unroll
        for (int w = 0; w < 8; w++) s += blk_p[w][threadIdx.x];
        atomicAdd(&g_prob_sums[threadIdx.x], s);
    } else if (threadIdx.x == 8) {
        float s = 0.f;
#pragma unroll
        for (int w = 0; w < 8; w++) s += blk_z[w];
        atomicAdd(&g_zsum, s);
    }
}

// ---------------- capacity assignment: warp-scan ----------------
__global__ void __launch_bounds__(1024) assign_kernel(float* __restrict__ out, int write_tail) {
    __shared__ int warpTot[32][E_NUM];
    __shared__ int warpPre[32][E_NUM];
    __shared__ int tot[E_NUM];

    const int tid  = threadIdx.x;
    const int wid  = tid >> 5;
    const int lane = tid & 31;
    const int base = tid * 8;

    int4 t0 = ((const int4*)g_topi)[tid * 2];
    int4 t1 = ((const int4*)g_topi)[tid * 2 + 1];
    int eidx[8] = {t0.x, t0.y, t0.z, t0.w, t1.x, t1.y, t1.z, t1.w};

    int cnt[E_NUM];
#pragma unroll
    for (int e = 0; e < E_NUM; e++) cnt[e] = 0;
#pragma unroll
    for (int j = 0; j < 8; j++) cnt[eidx[j]]++;

    int pre[E_NUM];
#pragma unroll
    for (int e = 0; e < E_NUM; e++) {
        int s = cnt[e];
#pragma unroll
        for (int off = 1; off < 32; off <<= 1) {
            int n = __shfl_up_sync(0xFFFFFFFFu, s, off);
            if (lane >= off) s += n;
        }
        pre[e] = s - cnt[e];
        if (lane == 31) warpTot[wid][e] = s;
    }
    __syncthreads();

    if (wid == 0) {
#pragma unroll
        for (int e = 0; e < E_NUM; e++) {
            int v = warpTot[lane][e];
            int s = v;
#pragma unroll
            for (int off = 1; off < 32; off <<= 1) {
                int n = __shfl_up_sync(0xFFFFFFFFu, s, off);
                if (lane >= off) s += n;
            }
            warpPre[lane][e] = s - v;
            if (lane == 31) tot[e] = s;
        }
    }
    __syncthreads();

    int run[E_NUM];
#pragma unroll
    for (int e = 0; e < E_NUM; e++) run[e] = warpPre[wid][e] + pre[e];
#pragma unroll
    for (int j = 0; j < 8; j++) {
        const int idx = base + j;
        const int e = eidx[j];
        const int r = run[e]++;
        if (r < CAPACITY) {
            g_rank[idx] = r;
            g_slot[e * CAPACITY + r] = idx;
        } else {
            g_rank[idx] = -1;
        }
    }

    if (tid < E_NUM) {
        int kc = tot[tid] < CAPACITY ? tot[tid] : CAPACITY;
        g_kcnt[tid]   = kc;
        g_blkcnt[tid] = (kc + 127) >> 7;
    }
    if (tid == 0 && write_tail) {
        float lb = 0.f;
#pragma unroll
        for (int e = 0; e < E_NUM; e++) {
            int kc = tot[e] < CAPACITY ? tot[e] : CAPACITY;
            lb += (g_prob_sums[e] / (float)T_TOK) *
                  ((float)kc / (float)(T_TOK * K_TOP));
        }
        lb *= (float)E_NUM;
        out[(size_t)T_TOK * D_MODEL]     = lb;
        out[(size_t)T_TOK * D_MODEL + 1] = g_zsum / (float)T_TOK;
    }
}

// ---------------- dispatch: only filled slots ----------------
__global__ void dispatch_kernel(const float* __restrict__ x) {
    const int e = blockIdx.y;
    const int r = blockIdx.x;
    if (r >= g_kcnt[e]) return;
    const int slot = e * CAPACITY + r;
    const int j = g_slot[slot];
    const int t = j & (T_TOK - 1);
    float4 v = ((const float4*)(x + (size_t)t * D_MODEL))[threadIdx.x];
    __half2 h0 = __floats2half2_rn(v.x, v.y);
    __half2 h1 = __floats2half2_rn(v.z, v.w);
    uint2 o;
    o.x = *(uint32_t*)&h0;
    o.y = *(uint32_t*)&h1;
    ((uint2*)(g_xe + (size_t)slot * D_MODEL))[threadIdx.x] = o;
}

// ---------------- tf32 warp-MMA GEMM, fp16 A AND fp16 B ------------------
#define AWSTR 12
#define ASZW  (128 * AWSTR)
#define BWSTR 68
#define BSZW  (16 * BWSTR)
#define GEMM_SMEM ((3 * (ASZW + BSZW)) * 4)

template<bool FIRST>
__global__ void __launch_bounds__(256, 2) gemm_mma_kernel(const __half* __restrict__ Wh,
                                                          float* __restrict__ out) {
    constexpr int Kd = FIRST ? D_MODEL : H_DIM;
    constexpr int Nt = FIRST ? H_DIM   : D_MODEL;
    constexpr int NIT = Kd / 16;

    const int e = blockIdx.z;
    if ((int)blockIdx.y >= g_blkcnt[e]) return;

    extern __shared__ __align__(16) uint32_t smw[];
    uint32_t* Asm = smw;
    uint32_t* Bsm = smw + 3 * ASZW;

    const int tid  = threadIdx.x;
    const int wid  = tid >> 5;
    const int lane = tid & 31;
    const int gid  = lane >> 2;
    const int tig  = lane & 3;
    const int warpM = wid & 1;
    const int warpN = wid >> 1;
    const int sh   = (tig & 1) * 16;
    const int wsel = tig >> 1;
    const int shb  = (gid & 1) * 16;
    const int bw0  = warpN * 16 + (gid >> 1);

    const int row0 = blockIdx.y * 128;
    const int col0 = blockIdx.x * 128;

    const __half* Ab = (FIRST ? g_xe : g_h) + (size_t)e * CAPACITY * Kd + (size_t)row0 * Kd;
    const __half* Bb = Wh + (size_t)e * Kd * Nt + col0;

    const int arow = tid >> 1;
    const int ach  = tid & 1;
    const __half* Aptr = Ab + (size_t)arow * Kd + ach * 8;
    const uint32_t aBase = (uint32_t)__cvta_generic_to_shared(Asm)
                         + (arow * AWSTR + ach * 4) * 4;

    const int brow = tid >> 4;
    const int bch  = tid & 15;
    const __half* Bptr = Bb + (size_t)brow * Nt + bch * 8;
    const uint32_t bBase = (uint32_t)__cvta_generic_to_shared(Bsm)
                         + (brow * BWSTR + bch * 4) * 4;

    float c[4][4][4];
#pragma unroll
    for (int i = 0; i < 4; i++)
#pragma unroll
        for (int j = 0; j < 4; j++)
#pragma unroll
            for (int q = 0; q < 4; q++) c[i][j][q] = 0.f;

    // prologue: stages 0,1
#pragma unroll
    for (int p = 0; p < 2; p++) {
        CP16(aBase + (uint32_t)(p * ASZW * 4), Aptr + p * 16);
        CP16(bBase + (uint32_t)(p * BSZW * 4), Bptr + (size_t)p * 16 * Nt);
        CPCOMMIT();
    }

    int s = 0;
    for (int it = 0; it < NIT; it++) {
        CPWAIT1();
        __syncthreads();

        if (it + 2 < NIT) {
            const int sn = (s + 2 >= 3) ? s - 1 : s + 2;
            CP16(aBase + (uint32_t)(sn * ASZW * 4), Aptr + (it + 2) * 16);
            CP16(bBase + (uint32_t)(sn * BSZW * 4), Bptr + (size_t)(it + 2) * 16 * Nt);
        }
        CPCOMMIT();

        const uint32_t* as = Asm + s * ASZW;
        const uint32_t* bs = Bsm + s * BSZW;
#pragma unroll
        for (int ks = 0; ks < 16; ks += 8) {
            const int kw = (ks >> 1);
            uint32_t a[4][4], b[4][2];
#pragma unroll
            for (int i = 0; i < 4; i++) {
                const int r = warpM * 64 + i * 16 + gid;
                a[i][0] = h2f_bits(as[r * AWSTR + kw + wsel], sh);
                a[i][1] = h2f_bits(as[(r + 8) * AWSTR + kw + wsel], sh);
                a[i][2] = h2f_bits(as[r * AWSTR + kw + 2 + wsel], sh);
                a[i][3] = h2f_bits(as[(r + 8) * AWSTR + kw + 2 + wsel], sh);
            }
#pragma unroll
            for (int j = 0; j < 4; j++) {
                b[j][0] = h2f_bits(bs[(ks + tig) * BWSTR + bw0 + j * 4], shb);
                b[j][1] = h2f_bits(bs[(ks + tig + 4) * BWSTR + bw0 + j * 4], shb);
            }
#pragma unroll
            for (int i = 0; i < 4; i++)
#pragma unroll
                for (int j = 0; j < 4; j++)
                    MMA_TF32(c[i][j], a[i], b[j]);
        }
        s = (s + 1 >= 3) ? 0 : s + 1;
    }

    // epilogue
    if (FIRST) {
        __half* Ch = g_h + (size_t)e * CAPACITY * Nt;
#pragma unroll
        for (int i = 0; i < 4; i++) {
            const int r = row0 + warpM * 64 + i * 16 + gid;
#pragma unroll
            for (int j = 0; j < 4; j++) {
                const int n = col0 + warpN * 32 + j * 8 + tig * 2;
                __half2 h0 = __floats2half2_rn(gelu_exact(c[i][j][0]), gelu_exact(c[i][j][1]));
                __half2 h1 = __floats2half2_rn(gelu_exact(c[i][j][2]), gelu_exact(c[i][j][3]));
                *(__half2*)&Ch[(size_t)r * Nt + n]       = h0;
                *(__half2*)&Ch[(size_t)(r + 8) * Nt + n] = h1;
            }
        }
    } else {
        const int kc = g_kcnt[e];
#pragma unroll
        for (int i = 0; i < 4; i++) {
            const int r0 = row0 + warpM * 64 + i * 16 + gid;
            const int r1 = r0 + 8;
            const bool k0 = r0 < kc;
            const bool k1 = r1 < kc;
            const int j0 = k0 ? g_slot[e * CAPACITY + r0] : 0;
            const int j1 = k1 ? g_slot[e * CAPACITY + r1] : 0;
            const float w0 = k0 ? g_p[j0] : 0.f;
            const float w1 = k1 ? g_p[j1] : 0.f;
            float* o0 = out + (size_t)(j0 & (T_TOK - 1)) * D_MODEL;
            float* o1 = out + (size_t)(j1 & (T_TOK - 1)) * D_MODEL;
#pragma unroll
            for (int j = 0; j < 4; j++) {
                const int n = col0 + warpN * 32 + j * 8 + tig * 2;
                if (k0) {
                    atomicAdd(o0 + n,     w0 * c[i][j][0]);
                    atomicAdd(o0 + n + 1, w0 * c[i][j][1]);
                }
                if (k1) {
                    atomicAdd(o1 + n,     w1 * c[i][j][2]);
                    atomicAdd(o1 + n + 1, w1 * c[i][j][3]);
                }
            }
        }
    }
}

// ---------------- launch ----------------
extern "C" void kernel_launch(void* const* d_in, const int* in_sizes, int n_in,
                              void* d_out, int out_size) {
    const float* x     = (const float*)d_in[0];
    const float* wg    = (const float*)d_in[1];
    const float* wfc   = (const float*)d_in[2];   // [E, D, HID]
    const float* wproj = (const float*)d_in[3];   // [E, HID, D]
    float* out = (float*)d_out;
    const int write_tail = (out_size >= T_TOK * D_MODEL + 2);

    static cudaStream_t s_side = nullptr;
    static cudaEvent_t  e_fork = nullptr, e_join = nullptr;
    static int attr_done = 0;
    if (!attr_done) {
        cudaFuncSetAttribute((const void*)gemm_mma_kernel<true>,
                             cudaFuncAttributeMaxDynamicSharedMemorySize, GEMM_SMEM);
        cudaFuncSetAttribute((const void*)gemm_mma_kernel<false>,
                             cudaFuncAttributeMaxDynamicSharedMemorySize, GEMM_SMEM);
        cudaStreamCreateWithFlags(&s_side, cudaStreamNonBlocking);
        cudaEventCreateWithFlags(&e_fork, cudaEventDisableTiming);
        cudaEventCreateWithFlags(&e_join, cudaEventDisableTiming);
        attr_done = 1;
    }

    __half* wfch;   cudaGetSymbolAddress((void**)&wfch,   g_wfch);
    __half* wprojh; cudaGetSymbolAddress((void**)&wprojh, g_wprojh);
    const size_t wn4 = (size_t)E_NUM * D_MODEL * H_DIM / 4;

    // fork: side stream does weight conversion + output zeroing,
    // main stream does the router -> assign -> dispatch chain.
    init_kernel<<<1, 32>>>();
    cudaEventRecord(e_fork, 0);
    cudaStreamWaitEvent(s_side, e_fork, 0);

    wconv_kernel<<<2048, 256, 0, s_side>>>(wfc,   wfch,   wn4);
    wconv_kernel<<<2048, 256, 0, s_side>>>(wproj, wprojh, wn4);
    zero_out_kernel<<<1024, 256, 0, s_side>>>(out);
    cudaEventRecord(e_join, s_side);

    router_kernel<<<T_TOK / 8, 256>>>(x, wg);
    assign_kernel<<<1, 1024>>>(out, write_tail);
    dispatch_kernel<<<dim3(CAPACITY, E_NUM), 256>>>(x);

    // join before GEMMs (GEMM1 needs wfch; GEMM2 needs wprojh + zeroed out)
    cudaStreamWaitEvent(0, e_join, 0);

    gemm_mma_kernel<true ><<<dim3(H_DIM / 128, CAPACITY / 128, E_NUM), 256, GEMM_SMEM>>>(wfch, out);
    gemm_mma_kernel<false><<<dim3(D_MODEL / 128, CAPACITY / 128, E_NUM), 256, GEMM_SMEM>>>(wprojh, out);
}

// round 16
// speedup vs baseline: 1.0735x; 1.0735x over previous
#include <cuda_runtime.h>
#include <cuda_fp16.h>
#include <cstdint>
#include <cmath>

// ---------------- problem constants ----------------
#define T_TOK   4096
#define D_MODEL 1024
#define E_NUM   8
#define K_TOP   2
#define CAPACITY 1280
#define H_DIM   4096
#define NYMAX   (CAPACITY / 128)

// ---------------- device scratch ----------------
__device__ __half g_xe   [(size_t)E_NUM * CAPACITY * D_MODEL];
__device__ __half g_h    [(size_t)E_NUM * CAPACITY * H_DIM];
__device__ __half g_wfch [(size_t)E_NUM * D_MODEL * H_DIM];
__device__ __half g_wprojh[(size_t)E_NUM * H_DIM * D_MODEL];
__device__ int   g_topi[K_TOP * T_TOK];
__device__ float g_p   [K_TOP * T_TOK];
__device__ int   g_rank[K_TOP * T_TOK];
__device__ int   g_slot[E_NUM * CAPACITY];
__device__ int   g_kcnt[E_NUM];
__device__ int   g_blkcnt[E_NUM];
__device__ float g_prob_sums[E_NUM];
__device__ float g_zsum;

// ---------------- helpers ----------------
__device__ __forceinline__ float gelu_exact(float v) {
    return 0.5f * v * (1.f + erff(v * 0.70710678118654752440f));
}
__device__ __forceinline__ uint32_t h2f_bits(uint32_t w, int sh) {
    __half h = __ushort_as_half((unsigned short)(w >> sh));
    return __float_as_uint(__half2float(h));
}

#define CP16(dst, src) \
    asm volatile("cp.async.cg.shared.global [%0], [%1], 16;" \
                 :: "r"(dst), "l"(src) : "memory")
#define CPCOMMIT() asm volatile("cp.async.commit_group;" ::: "memory")
#define CPWAIT1()  asm volatile("cp.async.wait_group 1;" ::: "memory")

#define MMA_TF32(c, a, b) \
    asm volatile("mma.sync.aligned.m16n8k8.row.col.f32.tf32.tf32.f32 " \
                 "{%0,%1,%2,%3}, {%4,%5,%6,%7}, {%8,%9}, {%0,%1,%2,%3};" \
                 : "+f"((c)[0]), "+f"((c)[1]), "+f"((c)[2]), "+f"((c)[3]) \
                 : "r"((a)[0]), "r"((a)[1]), "r"((a)[2]), "r"((a)[3]), \
                   "r"((b)[0]), "r"((b)[1]))

// ---------------- weight convert: fp32 -> fp16 elementwise ---------------
__global__ void wconv_kernel(const float* __restrict__ src, __half* __restrict__ dst,
                             size_t n4) {
    const float4* s4 = (const float4*)src;
    uint2* d4 = (uint2*)dst;
    for (size_t i = (size_t)blockIdx.x * blockDim.x + threadIdx.x; i < n4;
         i += (size_t)gridDim.x * blockDim.x) {
        float4 v = s4[i];
        __half2 h0 = __floats2half2_rn(v.x, v.y);
        __half2 h1 = __floats2half2_rn(v.z, v.w);
        uint2 o;
        o.x = *(uint32_t*)&h0;
        o.y = *(uint32_t*)&h1;
        d4[i] = o;
    }
}

// ---------------- zero output ----------------
__global__ void zero_out_kernel(float* __restrict__ out) {
    const size_t n = (size_t)T_TOK * D_MODEL / 4;
    float4 z = make_float4(0.f, 0.f, 0.f, 0.f);
    float4* p = (float4*)out;
    for (size_t i = (size_t)blockIdx.x * blockDim.x + threadIdx.x; i < n;
         i += (size_t)gridDim.x * blockDim.x)
        p[i] = z;
}

// ---------------- init: loss accumulators ----------------
__global__ void init_kernel() {
    const int i = threadIdx.x;
    if (i < E_NUM) g_prob_sums[i] = 0.f;
    if (i == 0)    g_zsum = 0.f;
}

// ---------------- router: warp-per-token ----------------
__global__ void __launch_bounds__(256) router_kernel(const float* __restrict__ x,
                                                     const float* __restrict__ wg) {
    const int wid  = threadIdx.x >> 5;
    const int lane = threadIdx.x & 31;
    const int t    = blockIdx.x * 8 + wid;

    float acc[E_NUM];
#pragma unroll
    for (int e = 0; e < E_NUM; e++) acc[e] = 0.f;

    const float4* x4 = (const float4*)(x + (size_t)t * D_MODEL);
#pragma unroll
    for (int p = 0; p < 8; p++) {
        const int d4 = p * 32 + lane;
        float4 v = x4[d4];
        const float* w = wg + (size_t)d4 * 4 * E_NUM;
#pragma unroll
        for (int e = 0; e < E_NUM; e++) acc[e] += v.x * w[e];
#pragma unroll
        for (int e = 0; e < E_NUM; e++) acc[e] += v.y * w[E_NUM + e];
#pragma unroll
        for (int e = 0; e < E_NUM; e++) acc[e] += v.z * w[2 * E_NUM + e];
#pragma unroll
        for (int e = 0; e < E_NUM; e++) acc[e] += v.w * w[3 * E_NUM + e];
    }
#pragma unroll
    for (int off = 16; off > 0; off >>= 1)
#pragma unroll
        for (int e = 0; e < E_NUM; e++)
            acc[e] += __shfl_xor_sync(0xFFFFFFFFu, acc[e], off);

    __shared__ float blk_p[8][E_NUM];
    __shared__ float blk_z[8];
    if (lane == 0) {
        float l[E_NUM];
#pragma unroll
        for (int e = 0; e < E_NUM; e++) l[e] = acc[e];
        float m = l[0];
#pragma unroll
        for (int e = 1; e < E_NUM; e++) m = fmaxf(m, l[e]);
        float se = 0.f;
#pragma unroll
        for (int e = 0; e < E_NUM; e++) se += expf(l[e] - m);
        float inv = 1.f / se;
#pragma unroll
        for (int e = 0; e < E_NUM; e++) blk_p[wid][e] = expf(l[e] - m) * inv;
        float lse = m + logf(se);
        blk_z[wid] = lse * lse;

        float v1 = -3.4e38f, v2 = -3.4e38f;
        int i1 = 0, i2 = 0;
#pragma unroll
        for (int e = 0; e < E_NUM; e++) {
            float v = l[e];
            if (v > v1) { v2 = v1; i2 = i1; v1 = v; i1 = e; }
            else if (v > v2) { v2 = v; i2 = e; }
        }
        float e2 = expf(v2 - v1);
        float s2 = 1.f + e2;
        g_topi[t]         = i1;
        g_topi[T_TOK + t] = i2;
        g_p[t]            = 1.f / s2;
        g_p[T_TOK + t]    = e2 / s2;
    }
    __syncthreads();
    if (threadIdx.x < E_NUM) {
        float s = 0.f;
#pragma unroll
        for (int w = 0; w < 8; w++) s += blk_p[w][threadIdx.x];
        atomicAdd(&g_prob_sums[threadIdx.x], s);
    } else if (threadIdx.x == 8) {
        float s = 0.f;
#pragma unroll
        for (int w = 0; w < 8; w++) s += blk_z[w];
        atomicAdd(&g_zsum, s);
    }
}

// ---------------- capacity assignment: warp-scan ----------------
__global__ void __launch_bounds__(1024) assign_kernel(float* __restrict__ out, int write_tail) {
    __shared__ int warpTot[32][E_NUM];
    __shared__ int warpPre[32][E_NUM];
    __shared__ int tot[E_NUM];

    const int tid  = threadIdx.x;
    const int wid  = tid >> 5;
    const int lane = tid & 31;
    const int base = tid * 8;

    int4 t0 = ((const int4*)g_topi)[tid * 2];
    int4 t1 = ((const int4*)g_topi)[tid * 2 + 1];
    int eidx[8] = {t0.x, t0.y, t0.z, t0.w, t1.x, t1.y, t1.z, t1.w};

    int cnt[E_NUM];
#pragma unroll
    for (int e = 0; e < E_NUM; e++) cnt[e] = 0;
#pragma unroll
    for (int j = 0; j < 8; j++) cnt[eidx[j]]++;

    int pre[E_NUM];
#pragma unroll
    for (int e = 0; e < E_NUM; e++) {
        int s = cnt[e];
#pragma unroll
        for (int off = 1; off < 32; off <<= 1) {
            int n = __shfl_up_sync(0xFFFFFFFFu, s, off);
            if (lane >= off) s += n;
        }
        pre[e] = s - cnt[e];
        if (lane == 31) warpTot[wid][e] = s;
    }
    __syncthreads();

    if (wid == 0) {
#pragma unroll
        for (int e = 0; e < E_NUM; e++) {
            int v = warpTot[lane][e];
            int s = v;
#pragma unroll
            for (int off = 1; off < 32; off <<= 1) {
                int n = __shfl_up_sync(0xFFFFFFFFu, s, off);
                if (lane >= off) s += n;
            }
            warpPre[lane][e] = s - v;
            if (lane == 31) tot[e] = s;
        }
    }
    __syncthreads();

    int run[E_NUM];
#pragma unroll
    for (int e = 0; e < E_NUM; e++) run[e] = warpPre[wid][e] + pre[e];
#pragma unroll
    for (int j = 0; j < 8; j++) {
        const int idx = base + j;
        const int e = eidx[j];
        const int r = run[e]++;
        if (r < CAPACITY) {
            g_rank[idx] = r;
            g_slot[e * CAPACITY + r] = idx;
        } else {
            g_rank[idx] = -1;
        }
    }

    if (tid < E_NUM) {
        int kc = tot[tid] < CAPACITY ? tot[tid] : CAPACITY;
        g_kcnt[tid]   = kc;
        g_blkcnt[tid] = (kc + 127) >> 7;
    }
    if (tid == 0 && write_tail) {
        float lb = 0.f;
#pragma unroll
        for (int e = 0; e < E_NUM; e++) {
            int kc = tot[e] < CAPACITY ? tot[e] : CAPACITY;
            lb += (g_prob_sums[e] / (float)T_TOK) *
                  ((float)kc / (float)(T_TOK * K_TOP));
        }
        lb *= (float)E_NUM;
        out[(size_t)T_TOK * D_MODEL]     = lb;
        out[(size_t)T_TOK * D_MODEL + 1] = g_zsum / (float)T_TOK;
    }
}

// ---------------- dispatch: 4 slots per block ----------------
__global__ void dispatch_kernel(const float* __restrict__ x) {
    const int e  = blockIdx.y;
    const int r0 = blockIdx.x * 4;
    const int kc = g_kcnt[e];
#pragma unroll
    for (int q = 0; q < 4; q++) {
        const int r = r0 + q;
        if (r >= kc) return;          // slots are contiguous: once past kc, done
        const int slot = e * CAPACITY + r;
        const int j = g_slot[slot];
        const int t = j & (T_TOK - 1);
        float4 v = ((const float4*)(x + (size_t)t * D_MODEL))[threadIdx.x];
        __half2 h0 = __floats2half2_rn(v.x, v.y);
        __half2 h1 = __floats2half2_rn(v.z, v.w);
        uint2 o;
        o.x = *(uint32_t*)&h0;
        o.y = *(uint32_t*)&h1;
        ((uint2*)(g_xe + (size_t)slot * D_MODEL))[threadIdx.x] = o;
    }
}

// ---------------- tf32 warp-MMA GEMM, fp16 A AND fp16 B ------------------
#define AWSTR 12
#define ASZW  (128 * AWSTR)
#define BWSTR 68
#define BSZW  (16 * BWSTR)
#define GEMM_SMEM ((3 * (ASZW + BSZW)) * 4)

template<bool FIRST>
__global__ void __launch_bounds__(256, 2) gemm_mma_kernel(const __half* __restrict__ Wh,
                                                          float* __restrict__ out) {
    constexpr int Kd = FIRST ? D_MODEL : H_DIM;
    constexpr int Nt = FIRST ? H_DIM   : D_MODEL;
    constexpr int NIT = Kd / 16;

    const int e = blockIdx.z;
    if ((int)blockIdx.y >= g_blkcnt[e]) return;

    extern __shared__ __align__(16) uint32_t smw[];
    uint32_t* Asm = smw;
    uint32_t* Bsm = smw + 3 * ASZW;

    const int tid  = threadIdx.x;
    const int wid  = tid >> 5;
    const int lane = tid & 31;
    const int gid  = lane >> 2;
    const int tig  = lane & 3;
    const int warpM = wid & 1;
    const int warpN = wid >> 1;
    const int sh   = (tig & 1) * 16;
    const int wsel = tig >> 1;
    const int shb  = (gid & 1) * 16;
    const int bw0  = warpN * 16 + (gid >> 1);

    const int row0 = blockIdx.y * 128;
    const int col0 = blockIdx.x * 128;

    const __half* Ab = (FIRST ? g_xe : g_h) + (size_t)e * CAPACITY * Kd + (size_t)row0 * Kd;
    const __half* Bb = Wh + (size_t)e * Kd * Nt + col0;

    const int arow = tid >> 1;
    const int ach  = tid & 1;
    const __half* Aptr = Ab + (size_t)arow * Kd + ach * 8;
    const uint32_t aBase = (uint32_t)__cvta_generic_to_shared(Asm)
                         + (arow * AWSTR + ach * 4) * 4;

    const int brow = tid >> 4;
    const int bch  = tid & 15;
    const __half* Bptr = Bb + (size_t)brow * Nt + bch * 8;
    const uint32_t bBase = (uint32_t)__cvta_generic_to_shared(Bsm)
                         + (brow * BWSTR + bch * 4) * 4;

    float c[4][4][4];
#pragma unroll
    for (int i = 0; i < 4; i++)
#pragma unroll
        for (int j = 0; j < 4; j++)
#pragma unroll
            for (int q = 0; q < 4; q++) c[i][j][q] = 0.f;

    // prologue: stages 0,1
#pragma unroll
    for (int p = 0; p < 2; p++) {
        CP16(aBase + (uint32_t)(p * ASZW * 4), Aptr + p * 16);
        CP16(bBase + (uint32_t)(p * BSZW * 4), Bptr + (size_t)p * 16 * Nt);
        CPCOMMIT();
    }

    int s = 0;
    for (int it = 0; it < NIT; it++) {
        CPWAIT1();
        __syncthreads();

        if (it + 2 < NIT) {
            const int sn = (s + 2 >= 3) ? s - 1 : s + 2;
            CP16(aBase + (uint32_t)(sn * ASZW * 4), Aptr + (it + 2) * 16);
            CP16(bBase + (uint32_t)(sn * BSZW * 4), Bptr + (size_t)(it + 2) * 16 * Nt);
        }
        CPCOMMIT();

        const uint32_t* as = Asm + s * ASZW;
        const uint32_t* bs = Bsm + s * BSZW;
#pragma unroll
        for (int ks = 0; ks < 16; ks += 8) {
            const int kw = (ks >> 1);
            uint32_t a[4][4], b[4][2];
#pragma unroll
            for (int i = 0; i < 4; i++) {
                const int r = warpM * 64 + i * 16 + gid;
                a[i][0] = h2f_bits(as[r * AWSTR + kw + wsel], sh);
                a[i][1] = h2f_bits(as[(r + 8) * AWSTR + kw + wsel], sh);
                a[i][2] = h2f_bits(as[r * AWSTR + kw + 2 + wsel], sh);
                a[i][3] = h2f_bits(as[(r + 8) * AWSTR + kw + 2 + wsel], sh);
            }
#pragma unroll
            for (int j = 0; j < 4; j++) {
                b[j][0] = h2f_bits(bs[(ks + tig) * BWSTR + bw0 + j * 4], shb);
                b[j][1] = h2f_bits(bs[(ks + tig + 4) * BWSTR + bw0 + j * 4], shb);
            }
#pragma unroll
            for (int i = 0; i < 4; i++)
#pragma unroll
                for (int j = 0; j < 4; j++)
                    MMA_TF32(c[i][j], a[i], b[j]);
        }
        s = (s + 1 >= 3) ? 0 : s + 1;
    }

    // epilogue
    if (FIRST) {
        __half* Ch = g_h + (size_t)e * CAPACITY * Nt;
#pragma unroll
        for (int i = 0; i < 4; i++) {
            const int r = row0 + warpM * 64 + i * 16 + gid;
#pragma unroll
            for (int j = 0; j < 4; j++) {
                const int n = col0 + warpN * 32 + j * 8 + tig * 2;
                __half2 h0 = __floats2half2_rn(gelu_exact(c[i][j][0]), gelu_exact(c[i][j][1]));
                __half2 h1 = __floats2half2_rn(gelu_exact(c[i][j][2]), gelu_exact(c[i][j][3]));
                *(__half2*)&Ch[(size_t)r * Nt + n]       = h0;
                *(__half2*)&Ch[(size_t)(r + 8) * Nt + n] = h1;
            }
        }
    } else {
        const int kc = g_kcnt[e];
#pragma unroll
        for (int i = 0; i < 4; i++) {
            const int r0 = row0 + warpM * 64 + i * 16 + gid;
            const int r1 = r0 + 8;
            const bool k0 = r0 < kc;
            const bool k1 = r1 < kc;
            const int j0 = k0 ? g_slot[e * CAPACITY + r0] : 0;
            const int j1 = k1 ? g_slot[e * CAPACITY + r1] : 0;
            const float w0 = k0 ? g_p[j0] : 0.f;
            const float w1 = k1 ? g_p[j1] : 0.f;
            float* o0 = out + (size_t)(j0 & (T_TOK - 1)) * D_MODEL;
            float* o1 = out + (size_t)(j1 & (T_TOK - 1)) * D_MODEL;
#pragma unroll
            for (int j = 0; j < 4; j++) {
                const int n = col0 + warpN * 32 + j * 8 + tig * 2;
                if (k0) {
                    atomicAdd(o0 + n,     w0 * c[i][j][0]);
                    atomicAdd(o0 + n + 1, w0 * c[i][j][1]);
                }
                if (k1) {
                    atomicAdd(o1 + n,     w1 * c[i][j][2]);
                    atomicAdd(o1 + n + 1, w1 * c[i][j][3]);
                }
            }
        }
    }
}

// ---------------- launch (serial, R14 schedule) ----------------
extern "C" void kernel_launch(void* const* d_in, const int* in_sizes, int n_in,
                              void* d_out, int out_size) {
    const float* x     = (const float*)d_in[0];
    const float* wg    = (const float*)d_in[1];
    const float* wfc   = (const float*)d_in[2];   // [E, D, HID]
    const float* wproj = (const float*)d_in[3];   // [E, HID, D]
    float* out = (float*)d_out;
    const int write_tail = (out_size >= T_TOK * D_MODEL + 2);

    static int attr_done = 0;
    if (!attr_done) {
        cudaFuncSetAttribute((const void*)gemm_mma_kernel<true>,
                             cudaFuncAttributeMaxDynamicSharedMemorySize, GEMM_SMEM);
        cudaFuncSetAttribute((const void*)gemm_mma_kernel<false>,
                             cudaFuncAttributeMaxDynamicSharedMemorySize, GEMM_SMEM);
        attr_done = 1;
    }

    __half* wfch;   cudaGetSymbolAddress((void**)&wfch,   g_wfch);
    __half* wprojh; cudaGetSymbolAddress((void**)&wprojh, g_wprojh);
    const size_t wn4 = (size_t)E_NUM * D_MODEL * H_DIM / 4;

    zero_out_kernel<<<1024, 256>>>(out);
    init_kernel<<<1, 32>>>();
    wconv_kernel<<<2048, 256>>>(wfc,   wfch,   wn4);
    wconv_kernel<<<2048, 256>>>(wproj, wprojh, wn4);
    router_kernel<<<T_TOK / 8, 256>>>(x, wg);
    assign_kernel<<<1, 1024>>>(out, write_tail);
    dispatch_kernel<<<dim3(CAPACITY / 4, E_NUM), 256>>>(x);

    gemm_mma_kernel<true ><<<dim3(H_DIM / 128, CAPACITY / 128, E_NUM), 256, GEMM_SMEM>>>(wfch, out);
    gemm_mma_kernel<false><<<dim3(D_MODEL / 128, CAPACITY / 128, E_NUM), 256, GEMM_SMEM>>>(wprojh, out);
}

// round 17
// speedup vs baseline: 1.1158x; 1.0394x over previous
#include <cuda_runtime.h>
#include <cuda_fp16.h>
#include <cstdint>
#include <cmath>

// ---------------- problem constants ----------------
#define T_TOK   4096
#define D_MODEL 1024
#define E_NUM   8
#define K_TOP   2
#define CAPACITY 1280
#define H_DIM   4096
#define NYMAX   (CAPACITY / 128)

// ---------------- device scratch ----------------
__device__ __half g_xe   [(size_t)E_NUM * CAPACITY * D_MODEL];
__device__ __half g_h    [(size_t)E_NUM * CAPACITY * H_DIM];
__device__ __half g_wfch [(size_t)E_NUM * D_MODEL * H_DIM];
__device__ __half g_wprojh[(size_t)E_NUM * H_DIM * D_MODEL];
__device__ int   g_topi[K_TOP * T_TOK];
__device__ float g_p   [K_TOP * T_TOK];
__device__ int   g_rank[K_TOP * T_TOK];
__device__ int   g_slot[E_NUM * CAPACITY];
__device__ int   g_kcnt[E_NUM];
__device__ int   g_blkcnt[E_NUM];
__device__ float g_prob_sums[E_NUM];
__device__ float g_zsum;

// ---------------- helpers ----------------
__device__ __forceinline__ float gelu_exact(float v) {
    return 0.5f * v * (1.f + erff(v * 0.70710678118654752440f));
}
__device__ __forceinline__ uint32_t h2f_bits(uint32_t w, int sh) {
    __half h = __ushort_as_half((unsigned short)(w >> sh));
    return __float_as_uint(__half2float(h));
}

#define CP16(dst, src) \
    asm volatile("cp.async.cg.shared.global [%0], [%1], 16;" \
                 :: "r"(dst), "l"(src) : "memory")
#define CPCOMMIT() asm volatile("cp.async.commit_group;" ::: "memory")
#define CPWAIT1()  asm volatile("cp.async.wait_group 1;" ::: "memory")

#define MMA_TF32(c, a, b) \
    asm volatile("mma.sync.aligned.m16n8k8.row.col.f32.tf32.tf32.f32 " \
                 "{%0,%1,%2,%3}, {%4,%5,%6,%7}, {%8,%9}, {%0,%1,%2,%3};" \
                 : "+f"((c)[0]), "+f"((c)[1]), "+f"((c)[2]), "+f"((c)[3]) \
                 : "r"((a)[0]), "r"((a)[1]), "r"((a)[2]), "r"((a)[3]), \
                   "r"((b)[0]), "r"((b)[1]))

// ---------------- weight convert: fp32 -> fp16 elementwise ---------------
__global__ void wconv_kernel(const float* __restrict__ src, __half* __restrict__ dst,
                             size_t n4) {
    const float4* s4 = (const float4*)src;
    uint2* d4 = (uint2*)dst;
    for (size_t i = (size_t)blockIdx.x * blockDim.x + threadIdx.x; i < n4;
         i += (size_t)gridDim.x * blockDim.x) {
        float4 v = s4[i];
        __half2 h0 = __floats2half2_rn(v.x, v.y);
        __half2 h1 = __floats2half2_rn(v.z, v.w);
        uint2 o;
        o.x = *(uint32_t*)&h0;
        o.y = *(uint32_t*)&h1;
        d4[i] = o;
    }
}

// ---------------- init: loss accumulators ----------------
__global__ void init_kernel() {
    const int i = threadIdx.x;
    if (i < E_NUM) g_prob_sums[i] = 0.f;
    if (i == 0)    g_zsum = 0.f;
}

// ---------------- router: warp-per-token ----------------
__global__ void __launch_bounds__(256) router_kernel(const float* __restrict__ x,
                                                     const float* __restrict__ wg) {
    const int wid  = threadIdx.x >> 5;
    const int lane = threadIdx.x & 31;
    const int t    = blockIdx.x * 8 + wid;

    float acc[E_NUM];
#pragma unroll
    for (int e = 0; e < E_NUM; e++) acc[e] = 0.f;

    const float4* x4 = (const float4*)(x + (size_t)t * D_MODEL);
#pragma unroll
    for (int p = 0; p < 8; p++) {
        const int d4 = p * 32 + lane;
        float4 v = x4[d4];
        const float* w = wg + (size_t)d4 * 4 * E_NUM;
#pragma unroll
        for (int e = 0; e < E_NUM; e++) acc[e] += v.x * w[e];
#pragma unroll
        for (int e = 0; e < E_NUM; e++) acc[e] += v.y * w[E_NUM + e];
#pragma unroll
        for (int e = 0; e < E_NUM; e++) acc[e] += v.z * w[2 * E_NUM + e];
#pragma unroll
        for (int e = 0; e < E_NUM; e++) acc[e] += v.w * w[3 * E_NUM + e];
    }
#pragma unroll
    for (int off = 16; off > 0; off >>= 1)
#pragma unroll
        for (int e = 0; e < E_NUM; e++)
            acc[e] += __shfl_xor_sync(0xFFFFFFFFu, acc[e], off);

    __shared__ float blk_p[8][E_NUM];
    __shared__ float blk_z[8];
    if (lane == 0) {
        float l[E_NUM];
#pragma unroll
        for (int e = 0; e < E_NUM; e++) l[e] = acc[e];
        float m = l[0];
#pragma unroll
        for (int e = 1; e < E_NUM; e++) m = fmaxf(m, l[e]);
        float se = 0.f;
#pragma unroll
        for (int e = 0; e < E_NUM; e++) se += expf(l[e] - m);
        float inv = 1.f / se;
#pragma unroll
        for (int e = 0; e < E_NUM; e++) blk_p[wid][e] = expf(l[e] - m) * inv;
        float lse = m + logf(se);
        blk_z[wid] = lse * lse;

        float v1 = -3.4e38f, v2 = -3.4e38f;
        int i1 = 0, i2 = 0;
#pragma unroll
        for (int e = 0; e < E_NUM; e++) {
            float v = l[e];
            if (v > v1) { v2 = v1; i2 = i1; v1 = v; i1 = e; }
            else if (v > v2) { v2 = v; i2 = e; }
        }
        float e2 = expf(v2 - v1);
        float s2 = 1.f + e2;
        g_topi[t]         = i1;
        g_topi[T_TOK + t] = i2;
        g_p[t]            = 1.f / s2;
        g_p[T_TOK + t]    = e2 / s2;
    }
    __syncthreads();
    if (threadIdx.x < E_NUM) {
        float s = 0.f;
#pragma unroll
        for (int w = 0; w < 8; w++) s += blk_p[w][threadIdx.x];
        atomicAdd(&g_prob_sums[threadIdx.x], s);
    } else if (threadIdx.x == 8) {
        float s = 0.f;
#pragma unroll
        for (int w = 0; w < 8; w++) s += blk_z[w];
        atomicAdd(&g_zsum, s);
    }
}

// ---------------- capacity assignment: warp-scan ----------------
__global__ void __launch_bounds__(1024) assign_kernel(float* __restrict__ out, int write_tail) {
    __shared__ int warpTot[32][E_NUM];
    __shared__ int warpPre[32][E_NUM];
    __shared__ int tot[E_NUM];

    const int tid  = threadIdx.x;
    const int wid  = tid >> 5;
    const int lane = tid & 31;
    const int base = tid * 8;

    int4 t0 = ((const int4*)g_topi)[tid * 2];
    int4 t1 = ((const int4*)g_topi)[tid * 2 + 1];
    int eidx[8] = {t0.x, t0.y, t0.z, t0.w, t1.x, t1.y, t1.z, t1.w};

    int cnt[E_NUM];
#pragma unroll
    for (int e = 0; e < E_NUM; e++) cnt[e] = 0;
#pragma unroll
    for (int j = 0; j < 8; j++) cnt[eidx[j]]++;

    int pre[E_NUM];
#pragma unroll
    for (int e = 0; e < E_NUM; e++) {
        int s = cnt[e];
#pragma unroll
        for (int off = 1; off < 32; off <<= 1) {
            int n = __shfl_up_sync(0xFFFFFFFFu, s, off);
            if (lane >= off) s += n;
        }
        pre[e] = s - cnt[e];
        if (lane == 31) warpTot[wid][e] = s;
    }
    __syncthreads();

    if (wid == 0) {
#pragma unroll
        for (int e = 0; e < E_NUM; e++) {
            int v = warpTot[lane][e];
            int s = v;
#pragma unroll
            for (int off = 1; off < 32; off <<= 1) {
                int n = __shfl_up_sync(0xFFFFFFFFu, s, off);
                if (lane >= off) s += n;
            }
            warpPre[lane][e] = s - v;
            if (lane == 31) tot[e] = s;
        }
    }
    __syncthreads();

    int run[E_NUM];
#pragma unroll
    for (int e = 0; e < E_NUM; e++) run[e] = warpPre[wid][e] + pre[e];
#pragma unroll
    for (int j = 0; j < 8; j++) {
        const int idx = base + j;
        const int e = eidx[j];
        const int r = run[e]++;
        if (r < CAPACITY) {
            g_rank[idx] = r;
            g_slot[e * CAPACITY + r] = idx;
        } else {
            g_rank[idx] = -1;
        }
    }

    if (tid < E_NUM) {
        int kc = tot[tid] < CAPACITY ? tot[tid] : CAPACITY;
        g_kcnt[tid]   = kc;
        g_blkcnt[tid] = (kc + 127) >> 7;
    }
    if (tid == 0 && write_tail) {
        float lb = 0.f;
#pragma unroll
        for (int e = 0; e < E_NUM; e++) {
            int kc = tot[e] < CAPACITY ? tot[e] : CAPACITY;
            lb += (g_prob_sums[e] / (float)T_TOK) *
                  ((float)kc / (float)(T_TOK * K_TOP));
        }
        lb *= (float)E_NUM;
        out[(size_t)T_TOK * D_MODEL]     = lb;
        out[(size_t)T_TOK * D_MODEL + 1] = g_zsum / (float)T_TOK;
    }
}

// ---------------- dispatch: 4 slots per block ----------------
__global__ void dispatch_kernel(const float* __restrict__ x) {
    const int e  = blockIdx.y;
    const int r0 = blockIdx.x * 4;
    const int kc = g_kcnt[e];
#pragma unroll
    for (int q = 0; q < 4; q++) {
        const int r = r0 + q;
        if (r >= kc) return;
        const int slot = e * CAPACITY + r;
        const int j = g_slot[slot];
        const int t = j & (T_TOK - 1);
        float4 v = ((const float4*)(x + (size_t)t * D_MODEL))[threadIdx.x];
        __half2 h0 = __floats2half2_rn(v.x, v.y);
        __half2 h1 = __floats2half2_rn(v.z, v.w);
        uint2 o;
        o.x = *(uint32_t*)&h0;
        o.y = *(uint32_t*)&h1;
        ((uint2*)(g_xe + (size_t)slot * D_MODEL))[threadIdx.x] = o;
    }
}

// ---------------- tf32 warp-MMA GEMM, fp16 A AND fp16 B ------------------
// FIRST additionally (grid-strided preamble, all blocks):
//   - converts wproj fp32 -> g_wprojh fp16
//   - zeroes out[0, T_TOK*D_MODEL)
#define AWSTR 12
#define ASZW  (128 * AWSTR)
#define BWSTR 68
#define BSZW  (16 * BWSTR)
#define GEMM_SMEM ((3 * (ASZW + BSZW)) * 4)
#define G1_GRID (E_NUM * NYMAX * (H_DIM / 128))   // 2560 blocks

template<bool FIRST>
__global__ void __launch_bounds__(256, 2) gemm_mma_kernel(const __half* __restrict__ Wh,
                                                          float* __restrict__ out,
                                                          const float* __restrict__ wproj_src) {
    constexpr int Kd = FIRST ? D_MODEL : H_DIM;
    constexpr int Nt = FIRST ? H_DIM   : D_MODEL;
    constexpr int NIT = Kd / 16;

    const int tid  = threadIdx.x;

    if (FIRST) {
        // aux preamble: deterministic grid-strided slices over all blocks
        const int bid = ((int)blockIdx.z * gridDim.y + (int)blockIdx.y) * gridDim.x
                      + (int)blockIdx.x;
        const size_t gstride = (size_t)G1_GRID * 256;
        // wproj fp32 -> fp16
        {
            const size_t n4 = (size_t)E_NUM * D_MODEL * H_DIM / 4;
            const float4* s4 = (const float4*)wproj_src;
            uint2* d4 = (uint2*)g_wprojh;
            for (size_t i = (size_t)bid * 256 + tid; i < n4; i += gstride) {
                float4 v = s4[i];
                __half2 h0 = __floats2half2_rn(v.x, v.y);
                __half2 h1 = __floats2half2_rn(v.z, v.w);
                uint2 o;
                o.x = *(uint32_t*)&h0;
                o.y = *(uint32_t*)&h1;
                d4[i] = o;
            }
        }
        // zero out
        {
            const size_t n4 = (size_t)T_TOK * D_MODEL / 4;
            float4 z = make_float4(0.f, 0.f, 0.f, 0.f);
            float4* p = (float4*)out;
            for (size_t i = (size_t)bid * 256 + tid; i < n4; i += gstride)
                p[i] = z;
        }
    }

    const int e = blockIdx.z;
    if ((int)blockIdx.y >= g_blkcnt[e]) return;

    extern __shared__ __align__(16) uint32_t smw[];
    uint32_t* Asm = smw;
    uint32_t* Bsm = smw + 3 * ASZW;

    const int wid  = tid >> 5;
    const int lane = tid & 31;
    const int gid  = lane >> 2;
    const int tig  = lane & 3;
    const int warpM = wid & 1;
    const int warpN = wid >> 1;
    const int sh   = (tig & 1) * 16;
    const int wsel = tig >> 1;
    const int shb  = (gid & 1) * 16;
    const int bw0  = warpN * 16 + (gid >> 1);

    const int row0 = blockIdx.y * 128;
    const int col0 = blockIdx.x * 128;

    const __half* Ab = (FIRST ? g_xe : g_h) + (size_t)e * CAPACITY * Kd + (size_t)row0 * Kd;
    const __half* Bb = Wh + (size_t)e * Kd * Nt + col0;

    const int arow = tid >> 1;
    const int ach  = tid & 1;
    const __half* Aptr = Ab + (size_t)arow * Kd + ach * 8;
    const uint32_t aBase = (uint32_t)__cvta_generic_to_shared(Asm)
                         + (arow * AWSTR + ach * 4) * 4;

    const int brow = tid >> 4;
    const int bch  = tid & 15;
    const __half* Bptr = Bb + (size_t)brow * Nt + bch * 8;
    const uint32_t bBase = (uint32_t)__cvta_generic_to_shared(Bsm)
                         + (brow * BWSTR + bch * 4) * 4;

    float c[4][4][4];
#pragma unroll
    for (int i = 0; i < 4; i++)
#pragma unroll
        for (int j = 0; j < 4; j++)
#pragma unroll
            for (int q = 0; q < 4; q++) c[i][j][q] = 0.f;

    // prologue: stages 0,1
#pragma unroll
    for (int p = 0; p < 2; p++) {
        CP16(aBase + (uint32_t)(p * ASZW * 4), Aptr + p * 16);
        CP16(bBase + (uint32_t)(p * BSZW * 4), Bptr + (size_t)p * 16 * Nt);
        CPCOMMIT();
    }

    int s = 0;
    for (int it = 0; it < NIT; it++) {
        CPWAIT1();
        __syncthreads();

        if (it + 2 < NIT) {
            const int sn = (s + 2 >= 3) ? s - 1 : s + 2;
            CP16(aBase + (uint32_t)(sn * ASZW * 4), Aptr + (it + 2) * 16);
            CP16(bBase + (uint32_t)(sn * BSZW * 4), Bptr + (size_t)(it + 2) * 16 * Nt);
        }
        CPCOMMIT();

        const uint32_t* as = Asm + s * ASZW;
        const uint32_t* bs = Bsm + s * BSZW;
#pragma unroll
        for (int ks = 0; ks < 16; ks += 8) {
            const int kw = (ks >> 1);
            uint32_t a[4][4], b[4][2];
#pragma unroll
            for (int i = 0; i < 4; i++) {
                const int r = warpM * 64 + i * 16 + gid;
                a[i][0] = h2f_bits(as[r * AWSTR + kw + wsel], sh);
                a[i][1] = h2f_bits(as[(r + 8) * AWSTR + kw + wsel], sh);
                a[i][2] = h2f_bits(as[r * AWSTR + kw + 2 + wsel], sh);
                a[i][3] = h2f_bits(as[(r + 8) * AWSTR + kw + 2 + wsel], sh);
            }
#pragma unroll
            for (int j = 0; j < 4; j++) {
                b[j][0] = h2f_bits(bs[(ks + tig) * BWSTR + bw0 + j * 4], shb);
                b[j][1] = h2f_bits(bs[(ks + tig + 4) * BWSTR + bw0 + j * 4], shb);
            }
#pragma unroll
            for (int i = 0; i < 4; i++)
#pragma unroll
                for (int j = 0; j < 4; j++)
                    MMA_TF32(c[i][j], a[i], b[j]);
        }
        s = (s + 1 >= 3) ? 0 : s + 1;
    }

    // epilogue
    if (FIRST) {
        __half* Ch = g_h + (size_t)e * CAPACITY * Nt;
#pragma unroll
        for (int i = 0; i < 4; i++) {
            const int r = row0 + warpM * 64 + i * 16 + gid;
#pragma unroll
            for (int j = 0; j < 4; j++) {
                const int n = col0 + warpN * 32 + j * 8 + tig * 2;
                __half2 h0 = __floats2half2_rn(gelu_exact(c[i][j][0]), gelu_exact(c[i][j][1]));
                __half2 h1 = __floats2half2_rn(gelu_exact(c[i][j][2]), gelu_exact(c[i][j][3]));
                *(__half2*)&Ch[(size_t)r * Nt + n]       = h0;
                *(__half2*)&Ch[(size_t)(r + 8) * Nt + n] = h1;
            }
        }
    } else {
        const int kc = g_kcnt[e];
#pragma unroll
        for (int i = 0; i < 4; i++) {
            const int r0 = row0 + warpM * 64 + i * 16 + gid;
            const int r1 = r0 + 8;
            const bool k0 = r0 < kc;
            const bool k1 = r1 < kc;
            const int j0 = k0 ? g_slot[e * CAPACITY + r0] : 0;
            const int j1 = k1 ? g_slot[e * CAPACITY + r1] : 0;
            const float w0 = k0 ? g_p[j0] : 0.f;
            const float w1 = k1 ? g_p[j1] : 0.f;
            float* o0 = out + (size_t)(j0 & (T_TOK - 1)) * D_MODEL;
            float* o1 = out + (size_t)(j1 & (T_TOK - 1)) * D_MODEL;
#pragma unroll
            for (int j = 0; j < 4; j++) {
                const int n = col0 + warpN * 32 + j * 8 + tig * 2;
                if (k0) {
                    atomicAdd(o0 + n,     w0 * c[i][j][0]);
                    atomicAdd(o0 + n + 1, w0 * c[i][j][1]);
                }
                if (k1) {
                    atomicAdd(o1 + n,     w1 * c[i][j][2]);
                    atomicAdd(o1 + n + 1, w1 * c[i][j][3]);
                }
            }
        }
    }
}

// ---------------- launch ----------------
extern "C" void kernel_launch(void* const* d_in, const int* in_sizes, int n_in,
                              void* d_out, int out_size) {
    const float* x     = (const float*)d_in[0];
    const float* wg    = (const float*)d_in[1];
    const float* wfc   = (const float*)d_in[2];   // [E, D, HID]
    const float* wproj = (const float*)d_in[3];   // [E, HID, D]
    float* out = (float*)d_out;
    const int write_tail = (out_size >= T_TOK * D_MODEL + 2);

    static int attr_done = 0;
    if (!attr_done) {
        cudaFuncSetAttribute((const void*)gemm_mma_kernel<true>,
                             cudaFuncAttributeMaxDynamicSharedMemorySize, GEMM_SMEM);
        cudaFuncSetAttribute((const void*)gemm_mma_kernel<false>,
                             cudaFuncAttributeMaxDynamicSharedMemorySize, GEMM_SMEM);
        attr_done = 1;
    }

    __half* wfch;   cudaGetSymbolAddress((void**)&wfch,   g_wfch);
    __half* wprojh; cudaGetSymbolAddress((void**)&wprojh, g_wprojh);
    const size_t wn4 = (size_t)E_NUM * D_MODEL * H_DIM / 4;

    init_kernel<<<1, 32>>>();
    wconv_kernel<<<2048, 256>>>(wfc, wfch, wn4);
    router_kernel<<<T_TOK / 8, 256>>>(x, wg);
    assign_kernel<<<1, 1024>>>(out, write_tail);
    dispatch_kernel<<<dim3(CAPACITY / 4, E_NUM), 256>>>(x);

    // GEMM1 also converts wproj -> g_wprojh and zeroes out[0, T*D) in its preamble
    gemm_mma_kernel<true ><<<dim3(H_DIM / 128, CAPACITY / 128, E_NUM), 256, GEMM_SMEM>>>(wfch, out, wproj);
    gemm_mma_kernel<false><<<dim3(D_MODEL / 128, CAPACITY / 128, E_NUM), 256, GEMM_SMEM>>>(wprojh, out, nullptr);
}